// round 12
// baseline (speedup 1.0000x reference)
#include <cuda_runtime.h>

// L_spa loss, fully fused single kernel (v3: full-chip fill).
// org, enhance: [32, 3, 512, 512] fp32.
// d[b,ph,pw] = (sum over 3ch x 4x4 block of (org-enh)) / 48   [32,128,128]
// loss = mean over pixels of sum of 4 shift-diff squares (zero padding).
//
// Vertical terms restructured: each interior pair (r,r+1) contributes
// 2*(d[r]-d[r+1])^2 assigned to the UPPER row; edges add d[0]^2, d[127]^2.
// => a band needs only ONE halo row (below), 6.25% redundant pool work.
//
// Grid 8 bands x 32 batch = 256 blocks x 512 threads, 2 CTAs/SM => all
// resident in one wave across 148 SMs (R2: 128 blocks, 20 SMs idle).

#define HWROW4   128                 // 512-float raw row = 128 float4
#define CH4      (512 * HWROW4)      // float4 per channel
#define IMG4     (3 * CH4)           // float4 per image
#define PH       128                 // pooled H = W
#define BAND     16                  // pooled rows per block
#define TROWS    (BAND + 1)          // +1 bottom halo
#define NPIX     (32 * PH * PH)
#define NBLOCKS  (8 * 32)

__device__ float    g_acc;     // zero-init; last block resets
__device__ unsigned g_count;   // zero-init; last block resets

__global__ void __launch_bounds__(512, 2) spa_fused_kernel(
    const float4* __restrict__ org, const float4* __restrict__ enh,
    float* __restrict__ out) {
    __shared__ float tile[TROWS][PH];      // 8704 B
    __shared__ float warp_sums[16];

    const int band = blockIdx.x;           // 0..7
    const int b    = blockIdx.y;           // 0..31
    const int tid  = threadIdx.x;
    const int s    = band * BAND;          // first pooled row of band
    const int ibase = b * IMG4;

    // ---- Phase 1: pool (org-enh) rows s .. s+16 (incl. 1 halo row)
    for (int i = tid; i < TROWS * PH; i += 512) {
        int r   = i >> 7;                  // 0..16
        int pw  = i & 127;
        int gph = s + r;
        float v = 0.0f;
        if (gph < PH) {
            int base = ibase + (gph * 4) * HWROW4 + pw;
            float sum = 0.0f;
#pragma unroll
            for (int c = 0; c < 3; c++) {
#pragma unroll
                for (int dy = 0; dy < 4; dy++) {
                    float4 o = __ldg(&org[base + c * CH4 + dy * HWROW4]);
                    float4 e = __ldg(&enh[base + c * CH4 + dy * HWROW4]);
                    sum += (o.x - e.x) + (o.y - e.y) + (o.z - e.z) + (o.w - e.w);
                }
            }
            v = sum * (1.0f / 48.0f);
        }
        tile[r][pw] = v;
    }
    __syncthreads();

    // ---- Phase 2: loss over the 16 owned rows
    float t = 0.0f;
#pragma unroll
    for (int k = 0; k < (BAND * PH) / 512; k++) {
        int i  = k * 512 + tid;
        int r  = i >> 7;                   // 0..15
        int pw = i & 127;
        int gr = s + r;
        float c  = tile[r][pw];
        float l  = (pw > 0)      ? tile[r][pw - 1] : 0.0f;
        float rr = (pw < PH - 1) ? tile[r][pw + 1] : 0.0f;
        t += (c - l) * (c - l) + (c - rr) * (c - rr);
        if (gr + 1 < PH) {                 // pair (gr, gr+1), counted x2
            float bl = tile[r + 1][pw];
            t += 2.0f * (c - bl) * (c - bl);
        } else {                           // bottom image edge
            t += c * c;
        }
        if (gr == 0) t += c * c;           // top image edge
    }

    // ---- Phase 3: block reduce + last-block finalize
#pragma unroll
    for (int off = 16; off > 0; off >>= 1)
        t += __shfl_down_sync(0xFFFFFFFFu, t, off);
    int lane = tid & 31, wid = tid >> 5;
    if (lane == 0) warp_sums[wid] = t;
    __syncthreads();
    if (wid == 0) {
        float v = (lane < 16) ? warp_sums[lane] : 0.0f;
#pragma unroll
        for (int off = 8; off > 0; off >>= 1)
            v += __shfl_down_sync(0xFFFFFFFFu, v, off);
        if (lane == 0) {
            atomicAdd(&g_acc, v);
            __threadfence();
            unsigned done = atomicAdd(&g_count, 1u);
            if (done == NBLOCKS - 1) {
                out[0] = g_acc * (1.0f / (float)NPIX);
                g_acc   = 0.0f;
                g_count = 0u;
            }
        }
    }
}

extern "C" void kernel_launch(void* const* d_in, const int* in_sizes, int n_in,
                              void* d_out, int out_size) {
    const float4* org = (const float4*)d_in[0];
    const float4* enh = (const float4*)d_in[1];
    float* out = (float*)d_out;
    spa_fused_kernel<<<dim3(8, 32), 512>>>(org, enh, out);
}